// round 1
// baseline (speedup 1.0000x reference)
#include <cuda_runtime.h>
#include <cstdint>
#include <cstddef>

// ---------------- problem constants ----------------
#define L_SEQ 301
#define BATCH 2
#define ROWSZ 602            // BATCH * L_SEQ
#define DM    768
#define DI    1536
#define DS    16
#define DR    48
#define XD    80             // DR + 2*DS
#define NPATCH 300
#define MIDP   150
#define KPATCH 12288         // 3*64*64

// ---------------- scratch (static device memory; no allocs) ----------------
__device__ float g_residual[ROWSZ*DM];
__device__ float g_hidden  [ROWSZ*DM];
__device__ float g_hnorm   [ROWSZ*DM];
__device__ float g_xz      [ROWSZ*2*DI];
__device__ float g_uc      [2*ROWSZ*DI];
__device__ float g_xdbl    [2*ROWSZ*XD];
__device__ float g_delta   [2*ROWSZ*DI];
__device__ float g_ys      [2*ROWSZ*DI];
__device__ float g_y       [ROWSZ*DI];

// buffer id resolvers (avoids host-side symbol-address lookups)
__device__ __forceinline__ const float* Abuf(int id) {
    switch (id) {
        case 0: return g_hnorm;
        case 1: return g_uc;
        case 2: return g_xdbl;
        default: return g_y;
    }
}
__device__ __forceinline__ float* Cbuf(int id) {
    switch (id) {
        case 0: return g_xz;
        case 1: return g_xdbl;
        case 2: return g_delta;
        default: return g_hidden;
    }
}

// ---------------- init: residual = tokens skeleton (cls row), hidden = 0 ----
__global__ void init_tokens_kernel(const float* __restrict__ cls,
                                   const float* __restrict__ pos) {
    int i = blockIdx.x * 256 + threadIdx.x;
    if (i >= ROWSZ*DM) return;
    g_hidden[i] = 0.f;
    int d = i % DM;
    int l = (i / DM) % L_SEQ;
    g_residual[i] = (l == MIDP) ? (cls[d] + pos[(size_t)MIDP*DM + d]) : 0.f;
}

// ---------------- patch embed GEMM (implicit im2col, NT), split-K=2 --------
// C(row m = b*300+p, col n = channel) += sum_k x_patch[m,k]*W[n,k]
// ks==0 adds patch_b + pos_embed. Writes into g_residual at token positions.
__global__ __launch_bounds__(128)
void patch_gemm_kernel(const float* __restrict__ X, const float* __restrict__ W,
                       const float* __restrict__ pb, const float* __restrict__ pos) {
    __shared__ float As[16][68];
    __shared__ float Bs[16][68];
    const int M = BATCH*NPATCH;
    const int Kc = KPATCH/2;
    int ks = blockIdx.z;
    int m0 = blockIdx.y * 64, n0 = blockIdx.x * 64;
    int tid = threadIdx.x;
    int ty = tid >> 4, tx = tid & 15;
    float acc[8][4] = {};
    for (int k0 = ks*Kc; k0 < ks*Kc + Kc; k0 += 16) {
#pragma unroll
        for (int i = 0; i < 2; i++) {
            int idx = tid + i*128;
            int row = idx >> 2, kq = idx & 3;
            int gm = m0 + row, gk = k0 + kq*4;
            float4 v = {0.f,0.f,0.f,0.f};
            if (gm < M) {
                int b = gm / NPATCH, p = gm % NPATCH;
                int py = p / 15, px = p % 15;
                int c = gk >> 12, ii = (gk >> 6) & 63, jj = gk & 63;
                v = *(const float4*)(X + (((size_t)(b*3 + c)*1280 + py*64 + ii)*960
                                           + px*64 + jj));
            }
            As[kq*4+0][row]=v.x; As[kq*4+1][row]=v.y;
            As[kq*4+2][row]=v.z; As[kq*4+3][row]=v.w;
            int gn = n0 + row;
            float4 w = *(const float4*)(W + (size_t)gn*KPATCH + gk);
            Bs[kq*4+0][row]=w.x; Bs[kq*4+1][row]=w.y;
            Bs[kq*4+2][row]=w.z; Bs[kq*4+3][row]=w.w;
        }
        __syncthreads();
#pragma unroll
        for (int kk = 0; kk < 16; kk++) {
            float4 a0 = *(const float4*)&As[kk][ty*8];
            float4 a1 = *(const float4*)&As[kk][ty*8+4];
            float4 b4 = *(const float4*)&Bs[kk][tx*4];
            float av[8] = {a0.x,a0.y,a0.z,a0.w,a1.x,a1.y,a1.z,a1.w};
            float bv[4] = {b4.x,b4.y,b4.z,b4.w};
#pragma unroll
            for (int i = 0; i < 8; i++)
#pragma unroll
                for (int j = 0; j < 4; j++) acc[i][j] += av[i]*bv[j];
        }
        __syncthreads();
    }
#pragma unroll
    for (int i = 0; i < 8; i++) {
        int gm = m0 + ty*8 + i;
        if (gm >= M) continue;
        int b = gm / NPATCH, p = gm % NPATCH;
        int l = (p < MIDP) ? p : p + 1;
        float* crow = &g_residual[((size_t)(b*L_SEQ + l))*DM];
#pragma unroll
        for (int j = 0; j < 4; j++) {
            int gn = n0 + tx*4 + j;
            float v = acc[i][j];
            if (ks == 0) v += pb[gn] + pos[(size_t)l*DM + gn];
            atomicAdd(&crow[gn], v);
        }
    }
}

// ---------------- generic NT GEMM: C[m,n] (+)= sum_k A[m,k]*B[n,k] ----------
// A = activation buffer (by id), B = weights (pointer pair selected by dir),
// optional split-K via atomicAdd (epilogue must be linear), dir via blockIdx.z.
// epi: 0 = store, 1 = *0.5, 2 = softplus(v + bias[n])
__global__ __launch_bounds__(128)
void gemm_nt_kernel(int M, int N, int K, int kSplit,
                    int a_id, int lda, size_t sAz,
                    const float* __restrict__ B0, const float* __restrict__ B1, int ldb,
                    int c_id, int ldc, size_t sCz,
                    const float* __restrict__ bias0, const float* __restrict__ bias1,
                    int epi) {
    __shared__ float As[16][68];
    __shared__ float Bs[16][68];
    int dir = blockIdx.z / kSplit;
    int ks  = blockIdx.z % kSplit;
    int Kc  = K / kSplit;
    const float* Ag = Abuf(a_id) + (size_t)dir * sAz;
    const float* Bg = dir ? B1 : B0;
    float* Cg = Cbuf(c_id) + (size_t)dir * sCz;
    const float* bias = dir ? bias1 : bias0;
    int m0 = blockIdx.y * 64, n0 = blockIdx.x * 64;
    int tid = threadIdx.x;
    int ty = tid >> 4, tx = tid & 15;
    float acc[8][4] = {};
    for (int k0 = ks*Kc; k0 < ks*Kc + Kc; k0 += 16) {
#pragma unroll
        for (int i = 0; i < 2; i++) {
            int idx = tid + i*128;
            int row = idx >> 2, kq = idx & 3;
            int gm = m0 + row, gk = k0 + kq*4;
            float4 va = {0.f,0.f,0.f,0.f};
            if (gm < M) va = *(const float4*)(Ag + (size_t)gm*lda + gk);
            As[kq*4+0][row]=va.x; As[kq*4+1][row]=va.y;
            As[kq*4+2][row]=va.z; As[kq*4+3][row]=va.w;
            int gn = n0 + row;
            float4 vb = {0.f,0.f,0.f,0.f};
            if (gn < N) vb = *(const float4*)(Bg + (size_t)gn*ldb + gk);
            Bs[kq*4+0][row]=vb.x; Bs[kq*4+1][row]=vb.y;
            Bs[kq*4+2][row]=vb.z; Bs[kq*4+3][row]=vb.w;
        }
        __syncthreads();
#pragma unroll
        for (int kk = 0; kk < 16; kk++) {
            float4 a0 = *(const float4*)&As[kk][ty*8];
            float4 a1 = *(const float4*)&As[kk][ty*8+4];
            float4 b4 = *(const float4*)&Bs[kk][tx*4];
            float av[8] = {a0.x,a0.y,a0.z,a0.w,a1.x,a1.y,a1.z,a1.w};
            float bv[4] = {b4.x,b4.y,b4.z,b4.w};
#pragma unroll
            for (int i = 0; i < 8; i++)
#pragma unroll
                for (int j = 0; j < 4; j++) acc[i][j] += av[i]*bv[j];
        }
        __syncthreads();
    }
#pragma unroll
    for (int i = 0; i < 8; i++) {
        int gm = m0 + ty*8 + i;
        if (gm >= M) continue;
#pragma unroll
        for (int j = 0; j < 4; j++) {
            int gn = n0 + tx*4 + j;
            if (gn >= N) continue;
            float v = acc[i][j];
            if (kSplit > 1) {
                if (epi == 1) v *= 0.5f;
                atomicAdd(&Cg[(size_t)gm*ldc + gn], v);
            } else {
                if (epi == 1) v *= 0.5f;
                else if (epi == 2) {
                    v += bias[gn];
                    v = (v > 20.f) ? v : log1pf(__expf(v));
                }
                Cg[(size_t)gm*ldc + gn] = v;
            }
        }
    }
}

// ---------------- fused residual-add + RMSNorm (one row per block) ---------
__global__ void rmsnorm_step_kernel(const float* __restrict__ nw) {
    int row = blockIdx.x;
    float* res = &g_residual[(size_t)row*DM];
    const float* hid = &g_hidden[(size_t)row*DM];
    float v[3]; float ss = 0.f;
#pragma unroll
    for (int i = 0; i < 3; i++) {
        int d = threadIdx.x + i*256;
        float t = res[d] + hid[d];
        v[i] = t; res[d] = t; ss += t*t;
    }
#pragma unroll
    for (int o = 16; o; o >>= 1) ss += __shfl_xor_sync(0xffffffffu, ss, o);
    __shared__ float sred[8];
    if ((threadIdx.x & 31) == 0) sred[threadIdx.x >> 5] = ss;
    __syncthreads();
    float total = 0.f;
#pragma unroll
    for (int i = 0; i < 8; i++) total += sred[i];
    float scale = rsqrtf(total * (1.f/DM) + 1e-5f);
#pragma unroll
    for (int i = 0; i < 3; i++) {
        int d = threadIdx.x + i*256;
        g_hnorm[(size_t)row*DM + d] = v[i] * scale * nw[d];
    }
}

// ---------------- final RMSNorm(residual + hidden) -> d_out ---------------
__global__ void final_norm_kernel(const float* __restrict__ nf, float* __restrict__ out) {
    int row = blockIdx.x;
    const float* res = &g_residual[(size_t)row*DM];
    const float* hid = &g_hidden[(size_t)row*DM];
    float v[3]; float ss = 0.f;
#pragma unroll
    for (int i = 0; i < 3; i++) {
        int d = threadIdx.x + i*256;
        float t = res[d] + hid[d];
        v[i] = t; ss += t*t;
    }
#pragma unroll
    for (int o = 16; o; o >>= 1) ss += __shfl_xor_sync(0xffffffffu, ss, o);
    __shared__ float sred[8];
    if ((threadIdx.x & 31) == 0) sred[threadIdx.x >> 5] = ss;
    __syncthreads();
    float total = 0.f;
#pragma unroll
    for (int i = 0; i < 8; i++) total += sred[i];
    float scale = rsqrtf(total * (1.f/DM) + 1e-5f);
#pragma unroll
    for (int i = 0; i < 3; i++) {
        int d = threadIdx.x + i*256;
        out[(size_t)row*DM + d] = v[i] * scale * nf[d];
    }
}

// ---------------- depthwise causal/anticausal conv + SiLU -----------------
__global__ void conv_silu_kernel(const float* __restrict__ cwf, const float* __restrict__ cbf,
                                 const float* __restrict__ cwb, const float* __restrict__ cbb) {
    int dir = blockIdx.y;
    int idx = blockIdx.x * 256 + threadIdx.x;
    if (idx >= ROWSZ*DI) return;
    int m = idx / DI, c = idx % DI;
    int b = m / L_SEQ, l = m % L_SEQ;
    const float* w = (dir ? cwb : cwf) + (size_t)c*4;
    float s = (dir ? cbb : cbf)[c];
#pragma unroll
    for (int tap = 0; tap < 4; tap++) {
        int lt = dir ? (l + 3 - tap) : (l - 3 + tap);
        if (lt >= 0 && lt < L_SEQ)
            s += w[tap] * g_xz[((size_t)(b*L_SEQ + lt))*(2*DI) + c];
    }
    g_uc[(size_t)dir*(ROWSZ*DI) + idx] = s / (1.f + __expf(-s));
}

// ---------------- selective scan: 16 lanes per channel, seq over L ---------
__global__ void scan_kernel(const float* __restrict__ Alog0, const float* __restrict__ Alog1,
                            const float* __restrict__ Dp0,  const float* __restrict__ Dp1) {
    int dir = blockIdx.z, b = blockIdx.y;
    int g = threadIdx.x >> 4, s = threadIdx.x & 15;
    int d = blockIdx.x * 16 + g;
    const float* Alog = dir ? Alog1 : Alog0;
    float A  = -__expf(Alog[(size_t)d*DS + s]);
    float Dv = (dir ? Dp1 : Dp0)[d];
    const float* dl = g_delta + (size_t)dir*(ROWSZ*DI);
    const float* uu = g_uc    + (size_t)dir*(ROWSZ*DI);
    const float* xd = g_xdbl  + (size_t)dir*(ROWSZ*XD);
    float* ys = g_ys + (size_t)dir*(ROWSZ*DI);
    float h = 0.f;
    int step = dir ? -1 : 1;
    int tt = dir ? (L_SEQ-1) : 0;
    size_t rowbase = (size_t)b * L_SEQ;
    size_t r = rowbase + tt;
    float delta = dl[r*DI + d], u = uu[r*DI + d];
    float Bv = xd[r*XD + DR + s], Cv = xd[r*XD + DR + DS + s];
    for (int it = 0; it < L_SEQ; it++) {
        float dn = 0.f, un = 0.f, Bn = 0.f, Cn = 0.f;
        int ttn = tt + step;
        if (it < L_SEQ-1) {
            size_t rn = rowbase + ttn;
            dn = dl[rn*DI + d]; un = uu[rn*DI + d];
            Bn = xd[rn*XD + DR + s]; Cn = xd[rn*XD + DR + DS + s];
        }
        h = __expf(delta * A) * h + (delta * u) * Bv;
        float y = h * Cv;
#pragma unroll
        for (int o = 8; o; o >>= 1) y += __shfl_xor_sync(0xffffffffu, y, o, 16);
        if (s == 0) ys[(rowbase + tt)*DI + d] = y + u * Dv;
        delta = dn; u = un; Bv = Bn; Cv = Cn; tt = ttn;
    }
}

// ---------------- combine: y = (ys_f + ys_b) * silu(z) --------------------
__global__ void combine_kernel() {
    int idx = blockIdx.x * 256 + threadIdx.x;
    if (idx >= ROWSZ*DI) return;
    int m = idx / DI, c = idx % DI;
    float z = g_xz[(size_t)m*(2*DI) + DI + c];
    float sv = z / (1.f + __expf(-z));
    g_y[idx] = (g_ys[idx] + g_ys[ROWSZ*DI + idx]) * sv;
}

// ---------------- zero helpers (split-K accumulators) ----------------------
__global__ void zero_xdbl_kernel() {
    int i = blockIdx.x * 256 + threadIdx.x;
    if (i < 2*ROWSZ*XD) g_xdbl[i] = 0.f;
}
__global__ void zero_hidden_kernel() {
    int i = blockIdx.x * 256 + threadIdx.x;
    if (i < ROWSZ*DM) g_hidden[i] = 0.f;
}

// ---------------- launcher -------------------------------------------------
extern "C" void kernel_launch(void* const* d_in, const int* in_sizes, int n_in,
                              void* d_out, int out_size) {
    const float* x        = (const float*)d_in[0];
    const float* patch_w  = (const float*)d_in[1];
    const float* patch_b  = (const float*)d_in[2];
    const float* cls_tok  = (const float*)d_in[3];
    const float* pos_emb  = (const float*)d_in[4];
    const float* norm_ws  = (const float*)d_in[5];
    const float* Win      = (const float*)d_in[6];
    const float* convw_f  = (const float*)d_in[7];
    const float* convb_f  = (const float*)d_in[8];
    const float* Wx_f     = (const float*)d_in[9];
    const float* Wdt_f    = (const float*)d_in[10];
    const float* bdt_f    = (const float*)d_in[11];
    const float* Alog_f   = (const float*)d_in[12];
    const float* Dskip_f  = (const float*)d_in[13];
    const float* convw_b  = (const float*)d_in[14];
    const float* convb_b  = (const float*)d_in[15];
    const float* Wx_b     = (const float*)d_in[16];
    const float* Wdt_b    = (const float*)d_in[17];
    const float* bdt_b    = (const float*)d_in[18];
    const float* Alog_b   = (const float*)d_in[19];
    const float* Dskip_b  = (const float*)d_in[20];
    const float* Wout     = (const float*)d_in[21];
    const float* normf_w  = (const float*)d_in[22];
    float* out = (float*)d_out;

    // tokens skeleton + hidden=0
    init_tokens_kernel<<<(ROWSZ*DM + 255)/256, 256>>>(cls_tok, pos_emb);
    // patch embed -> residual (split-K 2, atomic)
    patch_gemm_kernel<<<dim3(12, 10, 2), 128>>>(x, patch_w, patch_b, pos_emb);

    for (int layer = 0; layer < 8; layer++) {
        const float* nw   = norm_ws + (size_t)layer*DM;
        const float* WinL = Win  + (size_t)layer*2*DI*DM;
        const float* WoL  = Wout + (size_t)layer*DM*DI;
        const float* cwf = convw_f + (size_t)layer*DI*4;
        const float* cbf = convb_f + (size_t)layer*DI;
        const float* cwb = convw_b + (size_t)layer*DI*4;
        const float* cbb = convb_b + (size_t)layer*DI;
        const float* wxf = Wx_f + (size_t)layer*XD*DI;
        const float* wxb = Wx_b + (size_t)layer*XD*DI;
        const float* wdf = Wdt_f + (size_t)layer*DI*DR;
        const float* wdb = Wdt_b + (size_t)layer*DI*DR;
        const float* bdf = bdt_f + (size_t)layer*DI;
        const float* bdb = bdt_b + (size_t)layer*DI;
        const float* alf = Alog_f + (size_t)layer*DI*DS;
        const float* alb = Alog_b + (size_t)layer*DI*DS;
        const float* dsf = Dskip_f + (size_t)layer*DI;
        const float* dsb = Dskip_b + (size_t)layer*DI;

        // residual += hidden; h = rmsnorm(residual)
        rmsnorm_step_kernel<<<ROWSZ, 256>>>(nw);

        // xz = h @ Win^T   (602 x 3072, K=768)
        gemm_nt_kernel<<<dim3(48, 10, 1), 128>>>(
            ROWSZ, 2*DI, DM, 1, /*A=hnorm*/0, DM, 0,
            WinL, nullptr, DM, /*C=xz*/0, 2*DI, 0, nullptr, nullptr, 0);

        // depthwise conv + silu, both directions
        conv_silu_kernel<<<dim3((ROWSZ*DI + 255)/256, 2), 256>>>(cwf, cbf, cwb, cbb);

        // x_dbl = uc @ Wx^T  (602 x 80, K=1536), split-K 8, both dirs
        zero_xdbl_kernel<<<(2*ROWSZ*XD + 255)/256, 256>>>();
        gemm_nt_kernel<<<dim3(2, 10, 2*8), 128>>>(
            ROWSZ, XD, DI, 8, /*A=uc*/1, DI, (size_t)ROWSZ*DI,
            wxf, wxb, DI, /*C=xdbl*/1, XD, (size_t)ROWSZ*XD, nullptr, nullptr, 0);

        // delta = softplus(dt @ Wdt^T + bdt)  (602 x 1536, K=48), both dirs
        gemm_nt_kernel<<<dim3(24, 10, 2), 128>>>(
            ROWSZ, DI, DR, 1, /*A=xdbl*/2, XD, (size_t)ROWSZ*XD,
            wdf, wdb, DR, /*C=delta*/2, DI, (size_t)ROWSZ*DI, bdf, bdb, 2);

        // selective scan, both directions
        scan_kernel<<<dim3(DI/16, BATCH, 2), 256>>>(alf, alb, dsf, dsb);

        // y = (ys_f + ys_b) * silu(z)
        combine_kernel<<<(ROWSZ*DI + 255)/256, 256>>>();

        // hidden = 0.5 * y @ Wout^T  (602 x 768, K=1536), split-K 2
        zero_hidden_kernel<<<(ROWSZ*DM + 255)/256, 256>>>();
        gemm_nt_kernel<<<dim3(12, 10, 2), 128>>>(
            ROWSZ, DM, DI, 2, /*A=y*/3, DI, 0,
            WoL, nullptr, DI, /*C=hidden*/3, DM, 0, nullptr, nullptr, 1);
    }

    // out = rmsnorm(residual + hidden) * normf_w
    final_norm_kernel<<<ROWSZ, 256>>>(normf_w, out);
}

// round 2
// speedup vs baseline: 1.4912x; 1.4912x over previous
#include <cuda_runtime.h>
#include <cuda_bf16.h>
#include <cstdint>
#include <cstddef>

// ---------------- problem constants ----------------
#define L_SEQ 301
#define BATCH 2
#define ROWSZ 602            // BATCH * L_SEQ
#define DM    768
#define DI    1536
#define DS    16
#define DR    48
#define XD    80             // DR + 2*DS
#define NPATCH 300
#define MIDP   150
#define KPATCH 12288         // 3*64*64

// ---------------- fp32 scratch ----------------
__device__ float g_residual[ROWSZ*DM];
__device__ float g_hidden  [ROWSZ*DM];
__device__ float g_xz      [ROWSZ*2*DI];
__device__ float g_uc      [2*ROWSZ*DI];
__device__ float g_xdbl    [2*ROWSZ*XD];
__device__ float g_delta   [2*ROWSZ*DI];
__device__ float g_ys      [2*ROWSZ*DI];

// ---------------- bf16-split buffers ----------------
// weights
#define OFF_WIN  0ull
#define SZ_WIN   (8ull*3072*768)        // 18,874,368
#define OFF_WOUT (OFF_WIN + SZ_WIN)
#define SZ_WOUT  (8ull*768*1536)        // 9,437,184
#define OFF_WX   (OFF_WOUT + SZ_WOUT)
#define SZ_WX1   (8ull*80*1536)         // 983,040 (per dir)
#define OFF_WDT  (OFF_WX + 2*SZ_WX1)
#define SZ_WDT1  (8ull*1536*48)         // 589,824 (per dir)
#define OFF_PW   (OFF_WDT + 2*SZ_WDT1)
#define SZ_PW    (768ull*12288)         // 9,437,184
#define WTOT     (OFF_PW + SZ_PW)       // 40,894,464

__device__ __nv_bfloat16 w_hi[WTOT];
__device__ __nv_bfloat16 w_lo[WTOT];

// activations
#define OFF_HN   0ull
#define SZ_HN    ((size_t)ROWSZ*DM)     // 462,336
#define OFF_UC   (OFF_HN + SZ_HN)
#define SZ_UC1   ((size_t)ROWSZ*DI)     // 924,672 (per dir)
#define OFF_DT   (OFF_UC + 2*SZ_UC1)
#define SZ_DT1   ((size_t)ROWSZ*DR)     // 28,896 (per dir)
#define OFF_Y    (OFF_DT + 2*SZ_DT1)
#define SZ_Y     ((size_t)ROWSZ*DI)
#define OFF_XIM  (OFF_Y + SZ_Y)
#define SZ_XIM   (600ull*KPATCH)        // 7,372,800
#define ATOT     (OFF_XIM + SZ_XIM)

__device__ __nv_bfloat16 a_hi[ATOT];
__device__ __nv_bfloat16 a_lo[ATOT];

// ---------------- helpers ----------------
__device__ __forceinline__ void split1(float x, __nv_bfloat16& h, __nv_bfloat16& l) {
    __nv_bfloat16 hb = __float2bfloat16(x);
    h = hb;
    l = __float2bfloat16(x - __bfloat162float(hb));
}

__device__ __forceinline__ float* Cbuf(int id) {
    switch (id) {
        case 0: return g_xz;
        case 1: return g_xdbl;
        case 2: return g_delta;
        default: return g_hidden;
    }
}

#define LDSM4(r0,r1,r2,r3,addr) \
    asm volatile("ldmatrix.sync.aligned.m8n8.x4.shared.b16 {%0,%1,%2,%3}, [%4];" \
                 : "=r"(r0),"=r"(r1),"=r"(r2),"=r"(r3) : "r"(addr))

#define MMA16816(c,a,b) \
    asm volatile("mma.sync.aligned.m16n8k16.row.col.f32.bf16.bf16.f32 " \
                 "{%0,%1,%2,%3},{%4,%5,%6,%7},{%8,%9},{%0,%1,%2,%3};" \
                 : "+f"((c)[0]),"+f"((c)[1]),"+f"((c)[2]),"+f"((c)[3]) \
                 : "r"((a)[0]),"r"((a)[1]),"r"((a)[2]),"r"((a)[3]), \
                   "r"((b)[0]),"r"((b)[1]))

// ---------------- init: residual = pos + (bias | cls); hidden = 0 ----------
__global__ void init_tokens_kernel(const float* __restrict__ cls,
                                   const float* __restrict__ pos,
                                   const float* __restrict__ pb) {
    int i = blockIdx.x * 256 + threadIdx.x;
    if (i >= ROWSZ*DM) return;
    g_hidden[i] = 0.f;
    int d = i % DM;
    int l = (i / DM) % L_SEQ;
    float v = pos[(size_t)l*DM + d] + ((l == MIDP) ? cls[d] : pb[d]);
    g_residual[i] = v;
}

// ---------------- weight split: fp32 -> hi/lo bf16 -------------------------
__global__ void split_w_kernel(const float* __restrict__ src, int n4, size_t off) {
    int i = blockIdx.x * 256 + threadIdx.x;
    if (i >= n4) return;
    float4 v = ((const float4*)src)[i];
    size_t o = off + (size_t)i*4;
    split1(v.x, w_hi[o+0], w_lo[o+0]);
    split1(v.y, w_hi[o+1], w_lo[o+1]);
    split1(v.z, w_hi[o+2], w_lo[o+2]);
    split1(v.w, w_hi[o+3], w_lo[o+3]);
}

// ---------------- im2col + split for patch-embed A -------------------------
__global__ void im2col_split_kernel(const float* __restrict__ X) {
    int q = blockIdx.x * 256 + threadIdx.x;
    if (q >= 600*KPATCH/4) return;
    int m  = q / (KPATCH/4);
    int kq = (q % (KPATCH/4)) * 4;
    int c  = kq >> 12, ii = (kq >> 6) & 63, jj = kq & 63;
    int b = m / NPATCH, p = m % NPATCH;
    int py = p / 15, px = p % 15;
    float4 v = *(const float4*)(X + (((size_t)(b*3 + c)*1280 + py*64 + ii)*960
                                      + px*64 + jj));
    size_t o = OFF_XIM + (size_t)m*KPATCH + kq;
    split1(v.x, a_hi[o+0], a_lo[o+0]);
    split1(v.y, a_hi[o+1], a_lo[o+1]);
    split1(v.z, a_hi[o+2], a_lo[o+2]);
    split1(v.w, a_hi[o+3], a_lo[o+3]);
}

// ---------------- dt slice split (xdbl[:, :48] -> packed hi/lo) -----------
__global__ void split_dt_kernel() {
    int i = blockIdx.x * 256 + threadIdx.x;
    if (i >= 2*ROWSZ*DR) return;
    int dir = i / (ROWSZ*DR);
    int rem = i % (ROWSZ*DR);
    int r = rem / DR, c = rem % DR;
    float v = g_xdbl[(size_t)dir*ROWSZ*XD + (size_t)r*XD + c];
    split1(v, a_hi[OFF_DT + i], a_lo[OFF_DT + i]);
}

// ---------------- bf16-split tensor-core NT GEMM ---------------------------
// C[m,n] (+)= sum_k A[m,k]*B[n,k], 3-pass hi/lo. Block tile 128x128, BK=32.
// grid: (ceil(N/128), ceil(M/128), dirs*kSplit)
// epi: 0 store, 1 *0.5, 2 softplus(v+bias[n]), 3 atomicAdd into residual(patch)
#define BKP 40
__global__ __launch_bounds__(256)
void gemm_bf16_kernel(int M, int N, int K, int kSplit,
                      size_t aoff, size_t adirstr,
                      size_t boff, size_t bdirstr,
                      int c_id, int ldc, size_t cdirstr,
                      const float* __restrict__ bias0,
                      const float* __restrict__ bias1, int epi) {
    __shared__ __align__(16) uint16_t As_h[128*BKP];
    __shared__ __align__(16) uint16_t As_l[128*BKP];
    __shared__ __align__(16) uint16_t Bs_h[128*BKP];
    __shared__ __align__(16) uint16_t Bs_l[128*BKP];

    int dir = blockIdx.z / kSplit;
    int ks  = blockIdx.z % kSplit;
    int Kc  = K / kSplit;              // guaranteed %32==0 when kSplit>1
    int kbeg = ks * Kc;
    int kend = (kSplit > 1) ? (kbeg + Kc) : K;

    const __nv_bfloat16* Agh = a_hi + aoff + (size_t)dir*adirstr;
    const __nv_bfloat16* Agl = a_lo + aoff + (size_t)dir*adirstr;
    const __nv_bfloat16* Bgh = w_hi + boff + (size_t)dir*bdirstr;
    const __nv_bfloat16* Bgl = w_lo + boff + (size_t)dir*bdirstr;
    float* Cg = Cbuf(c_id) + (size_t)dir*cdirstr;
    const float* bias = dir ? bias1 : bias0;

    int m0 = blockIdx.y * 128, n0 = blockIdx.x * 128;
    int tid = threadIdx.x;
    int lane = tid & 31, warp = tid >> 5;
    int wm = (warp >> 2) * 64;
    int wn = (warp & 3) * 32;
    int lm = lane & 7, sel = lane >> 3;

    uint32_t bAh = (uint32_t)__cvta_generic_to_shared(As_h);
    uint32_t bAl = (uint32_t)__cvta_generic_to_shared(As_l);
    uint32_t bBh = (uint32_t)__cvta_generic_to_shared(Bs_h);
    uint32_t bBl = (uint32_t)__cvta_generic_to_shared(Bs_l);

    float acc[4][4][4];
#pragma unroll
    for (int i = 0; i < 4; i++)
#pragma unroll
        for (int j = 0; j < 4; j++)
#pragma unroll
            for (int q = 0; q < 4; q++) acc[i][j][q] = 0.f;

    for (int k0 = kbeg; k0 < kend; k0 += 32) {
        // load 128x32 A(hi,lo) and B(hi,lo) tiles
#pragma unroll
        for (int i = 0; i < 2; i++) {
            int idx = tid + i*256;
            int row = idx >> 2, c8 = idx & 3;
            int gk = k0 + c8*8;
            uint4 z = {0u,0u,0u,0u};
            int gm = m0 + row;
            uint4 vah = z, val = z;
            if (gm < M && gk < K) {
                const __nv_bfloat16* pa = Agh + (size_t)gm*K + gk;
                vah = *(const uint4*)pa;
                val = *(const uint4*)(Agl + (size_t)gm*K + gk);
            }
            *(uint4*)&As_h[row*BKP + c8*8] = vah;
            *(uint4*)&As_l[row*BKP + c8*8] = val;
            int gn = n0 + row;
            uint4 vbh = z, vbl = z;
            if (gn < N && gk < K) {
                vbh = *(const uint4*)(Bgh + (size_t)gn*K + gk);
                vbl = *(const uint4*)(Bgl + (size_t)gn*K + gk);
            }
            *(uint4*)&Bs_h[row*BKP + c8*8] = vbh;
            *(uint4*)&Bs_l[row*BKP + c8*8] = vbl;
        }
        __syncthreads();

#pragma unroll
        for (int kk = 0; kk < 2; kk++) {
            int ko = kk*16;
            uint32_t ah[4][4], al[4][4], bh[4][2], bl[4][2];
#pragma unroll
            for (int mt = 0; mt < 4; mt++) {
                int ar = wm + mt*16 + (sel & 1)*8 + lm;
                uint32_t off = (uint32_t)((ar*BKP + ko + (sel >> 1)*8) * 2);
                LDSM4(ah[mt][0], ah[mt][1], ah[mt][2], ah[mt][3], bAh + off);
                LDSM4(al[mt][0], al[mt][1], al[mt][2], al[mt][3], bAl + off);
            }
#pragma unroll
            for (int p = 0; p < 2; p++) {
                int br = wn + p*16 + (sel >> 1)*8 + lm;
                uint32_t off = (uint32_t)((br*BKP + ko + (sel & 1)*8) * 2);
                uint32_t r0, r1, r2, r3;
                LDSM4(r0, r1, r2, r3, bBh + off);
                bh[2*p][0] = r0; bh[2*p][1] = r1;
                bh[2*p+1][0] = r2; bh[2*p+1][1] = r3;
                LDSM4(r0, r1, r2, r3, bBl + off);
                bl[2*p][0] = r0; bl[2*p][1] = r1;
                bl[2*p+1][0] = r2; bl[2*p+1][1] = r3;
            }
#pragma unroll
            for (int mt = 0; mt < 4; mt++)
#pragma unroll
                for (int nt = 0; nt < 4; nt++) {
                    MMA16816(acc[mt][nt], ah[mt], bh[nt]);
                    MMA16816(acc[mt][nt], ah[mt], bl[nt]);
                    MMA16816(acc[mt][nt], al[mt], bh[nt]);
                }
        }
        __syncthreads();
    }

    // epilogue
    bool atomic = (kSplit > 1);
#pragma unroll
    for (int mt = 0; mt < 4; mt++) {
#pragma unroll
        for (int nt = 0; nt < 4; nt++) {
            int gm0 = m0 + wm + mt*16 + (lane >> 2);
            int gn0 = n0 + wn + nt*8 + (lane & 3)*2;
#pragma unroll
            for (int q = 0; q < 4; q++) {
                int gm = gm0 + (q >> 1)*8;
                int gn = gn0 + (q & 1);
                if (gm >= M || gn >= N) continue;
                float v = acc[mt][nt][q];
                if (epi == 3) {
                    int b = gm / NPATCH, p = gm % NPATCH;
                    int l = (p < MIDP) ? p : p + 1;
                    atomicAdd(&g_residual[((size_t)(b*L_SEQ + l))*DM + gn], v);
                    continue;
                }
                if (epi == 1) v *= 0.5f;
                if (atomic) {
                    atomicAdd(&Cg[(size_t)gm*ldc + gn], v);
                } else {
                    if (epi == 2) {
                        v += bias[gn];
                        v = (v > 20.f) ? v : log1pf(__expf(v));
                    }
                    Cg[(size_t)gm*ldc + gn] = v;
                }
            }
        }
    }
}

// ---------------- fused residual-add + RMSNorm + split ---------------------
__global__ void rmsnorm_step_kernel(const float* __restrict__ nw) {
    int row = blockIdx.x;
    float* res = &g_residual[(size_t)row*DM];
    const float* hid = &g_hidden[(size_t)row*DM];
    float v[3]; float ss = 0.f;
#pragma unroll
    for (int i = 0; i < 3; i++) {
        int d = threadIdx.x + i*256;
        float t = res[d] + hid[d];
        v[i] = t; res[d] = t; ss += t*t;
    }
#pragma unroll
    for (int o = 16; o; o >>= 1) ss += __shfl_xor_sync(0xffffffffu, ss, o);
    __shared__ float sred[8];
    if ((threadIdx.x & 31) == 0) sred[threadIdx.x >> 5] = ss;
    __syncthreads();
    float total = 0.f;
#pragma unroll
    for (int i = 0; i < 8; i++) total += sred[i];
    float scale = rsqrtf(total * (1.f/DM) + 1e-5f);
#pragma unroll
    for (int i = 0; i < 3; i++) {
        int d = threadIdx.x + i*256;
        float o = v[i] * scale * nw[d];
        size_t idx = OFF_HN + (size_t)row*DM + d;
        split1(o, a_hi[idx], a_lo[idx]);
    }
}

// ---------------- final RMSNorm(residual + hidden) -> d_out ---------------
__global__ void final_norm_kernel(const float* __restrict__ nf, float* __restrict__ out) {
    int row = blockIdx.x;
    const float* res = &g_residual[(size_t)row*DM];
    const float* hid = &g_hidden[(size_t)row*DM];
    float v[3]; float ss = 0.f;
#pragma unroll
    for (int i = 0; i < 3; i++) {
        int d = threadIdx.x + i*256;
        float t = res[d] + hid[d];
        v[i] = t; ss += t*t;
    }
#pragma unroll
    for (int o = 16; o; o >>= 1) ss += __shfl_xor_sync(0xffffffffu, ss, o);
    __shared__ float sred[8];
    if ((threadIdx.x & 31) == 0) sred[threadIdx.x >> 5] = ss;
    __syncthreads();
    float total = 0.f;
#pragma unroll
    for (int i = 0; i < 8; i++) total += sred[i];
    float scale = rsqrtf(total * (1.f/DM) + 1e-5f);
#pragma unroll
    for (int i = 0; i < 3; i++) {
        int d = threadIdx.x + i*256;
        out[(size_t)row*DM + d] = v[i] * scale * nf[d];
    }
}

// ---------------- depthwise conv + SiLU + split -----------------------------
__global__ void conv_silu_kernel(const float* __restrict__ cwf, const float* __restrict__ cbf,
                                 const float* __restrict__ cwb, const float* __restrict__ cbb) {
    int dir = blockIdx.y;
    int idx = blockIdx.x * 256 + threadIdx.x;
    if (idx >= ROWSZ*DI) return;
    int m = idx / DI, c = idx % DI;
    int b = m / L_SEQ, l = m % L_SEQ;
    const float* w = (dir ? cwb : cwf) + (size_t)c*4;
    float s = (dir ? cbb : cbf)[c];
#pragma unroll
    for (int tap = 0; tap < 4; tap++) {
        int lt = dir ? (l + 3 - tap) : (l - 3 + tap);
        if (lt >= 0 && lt < L_SEQ)
            s += w[tap] * g_xz[((size_t)(b*L_SEQ + lt))*(2*DI) + c];
    }
    float sv = s / (1.f + __expf(-s));
    size_t o = (size_t)dir*(ROWSZ*DI) + idx;
    g_uc[o] = sv;
    split1(sv, a_hi[OFF_UC + o], a_lo[OFF_UC + o]);
}

// ---------------- selective scan --------------------------------------------
__global__ void scan_kernel(const float* __restrict__ Alog0, const float* __restrict__ Alog1,
                            const float* __restrict__ Dp0,  const float* __restrict__ Dp1) {
    int dir = blockIdx.z, b = blockIdx.y;
    int g = threadIdx.x >> 4, s = threadIdx.x & 15;
    int d = blockIdx.x * 16 + g;
    const float* Alog = dir ? Alog1 : Alog0;
    float A  = -__expf(Alog[(size_t)d*DS + s]);
    float Dv = (dir ? Dp1 : Dp0)[d];
    const float* dl = g_delta + (size_t)dir*(ROWSZ*DI);
    const float* uu = g_uc    + (size_t)dir*(ROWSZ*DI);
    const float* xd = g_xdbl  + (size_t)dir*(ROWSZ*XD);
    float* ys = g_ys + (size_t)dir*(ROWSZ*DI);
    float h = 0.f;
    int step = dir ? -1 : 1;
    int tt = dir ? (L_SEQ-1) : 0;
    size_t rowbase = (size_t)b * L_SEQ;
    size_t r = rowbase + tt;
    float delta = dl[r*DI + d], u = uu[r*DI + d];
    float Bv = xd[r*XD + DR + s], Cv = xd[r*XD + DR + DS + s];
    for (int it = 0; it < L_SEQ; it++) {
        float dn = 0.f, un = 0.f, Bn = 0.f, Cn = 0.f;
        int ttn = tt + step;
        if (it < L_SEQ-1) {
            size_t rn = rowbase + ttn;
            dn = dl[rn*DI + d]; un = uu[rn*DI + d];
            Bn = xd[rn*XD + DR + s]; Cn = xd[rn*XD + DR + DS + s];
        }
        h = __expf(delta * A) * h + (delta * u) * Bv;
        float y = h * Cv;
#pragma unroll
        for (int o = 8; o; o >>= 1) y += __shfl_xor_sync(0xffffffffu, y, o, 16);
        if (s == 0) ys[(rowbase + tt)*DI + d] = y + u * Dv;
        delta = dn; u = un; Bv = Bn; Cv = Cn; tt = ttn;
    }
}

// ---------------- combine: y = (ys_f + ys_b) * silu(z), split --------------
__global__ void combine_kernel() {
    int idx = blockIdx.x * 256 + threadIdx.x;
    if (idx >= ROWSZ*DI) return;
    int m = idx / DI, c = idx % DI;
    float z = g_xz[(size_t)m*(2*DI) + DI + c];
    float sv = z / (1.f + __expf(-z));
    float yv = (g_ys[idx] + g_ys[(size_t)ROWSZ*DI + idx]) * sv;
    split1(yv, a_hi[OFF_Y + idx], a_lo[OFF_Y + idx]);
}

// ---------------- zero helpers ----------------------------------------------
__global__ void zero_xdbl_kernel() {
    int i = blockIdx.x * 256 + threadIdx.x;
    if (i < 2*ROWSZ*XD) g_xdbl[i] = 0.f;
}
__global__ void zero_hidden_kernel() {
    int i = blockIdx.x * 256 + threadIdx.x;
    if (i < ROWSZ*DM) g_hidden[i] = 0.f;
}

// ---------------- launcher ---------------------------------------------------
extern "C" void kernel_launch(void* const* d_in, const int* in_sizes, int n_in,
                              void* d_out, int out_size) {
    const float* x        = (const float*)d_in[0];
    const float* patch_w  = (const float*)d_in[1];
    const float* patch_b  = (const float*)d_in[2];
    const float* cls_tok  = (const float*)d_in[3];
    const float* pos_emb  = (const float*)d_in[4];
    const float* norm_ws  = (const float*)d_in[5];
    const float* Win      = (const float*)d_in[6];
    const float* convw_f  = (const float*)d_in[7];
    const float* convb_f  = (const float*)d_in[8];
    const float* Wx_f     = (const float*)d_in[9];
    const float* Wdt_f    = (const float*)d_in[10];
    const float* bdt_f    = (const float*)d_in[11];
    const float* Alog_f   = (const float*)d_in[12];
    const float* Dskip_f  = (const float*)d_in[13];
    const float* convw_b  = (const float*)d_in[14];
    const float* convb_b  = (const float*)d_in[15];
    const float* Wx_b     = (const float*)d_in[16];
    const float* Wdt_b    = (const float*)d_in[17];
    const float* bdt_b    = (const float*)d_in[18];
    const float* Alog_b   = (const float*)d_in[19];
    const float* Dskip_b  = (const float*)d_in[20];
    const float* Wout     = (const float*)d_in[21];
    const float* normf_w  = (const float*)d_in[22];
    float* out = (float*)d_out;

    auto g1 = [](size_t n) { return (unsigned)((n + 255) / 256); };

    // init residual (pos + bias / cls), hidden = 0
    init_tokens_kernel<<<g1(ROWSZ*DM), 256>>>(cls_tok, pos_emb, patch_b);

    // weight splits (per replay; pure bandwidth)
    split_w_kernel<<<g1(SZ_WIN/4), 256>>>(Win, (int)(SZ_WIN/4), OFF_WIN);
    split_w_kernel<<<g1(SZ_WOUT/4), 256>>>(Wout, (int)(SZ_WOUT/4), OFF_WOUT);
    split_w_kernel<<<g1(SZ_WX1/4), 256>>>(Wx_f, (int)(SZ_WX1/4), OFF_WX);
    split_w_kernel<<<g1(SZ_WX1/4), 256>>>(Wx_b, (int)(SZ_WX1/4), OFF_WX + SZ_WX1);
    split_w_kernel<<<g1(SZ_WDT1/4), 256>>>(Wdt_f, (int)(SZ_WDT1/4), OFF_WDT);
    split_w_kernel<<<g1(SZ_WDT1/4), 256>>>(Wdt_b, (int)(SZ_WDT1/4), OFF_WDT + SZ_WDT1);
    split_w_kernel<<<g1(SZ_PW/4), 256>>>(patch_w, (int)(SZ_PW/4), OFF_PW);

    // patch-embed A (im2col + split), then patch GEMM -> residual (atomic)
    im2col_split_kernel<<<g1(SZ_XIM/4), 256>>>(x);
    gemm_bf16_kernel<<<dim3(6, 5, 8), 256>>>(
        600, DM, KPATCH, 8,
        OFF_XIM, 0, OFF_PW, 0,
        /*c_id unused*/3, DM, 0, nullptr, nullptr, /*epi*/3);

    for (int layer = 0; layer < 8; layer++) {
        const float* nw  = norm_ws + (size_t)layer*DM;
        const float* cwf = convw_f + (size_t)layer*DI*4;
        const float* cbf = convb_f + (size_t)layer*DI;
        const float* cwb = convw_b + (size_t)layer*DI*4;
        const float* cbb = convb_b + (size_t)layer*DI;
        const float* bdf = bdt_f + (size_t)layer*DI;
        const float* bdb = bdt_b + (size_t)layer*DI;
        const float* alf = Alog_f + (size_t)layer*DI*DS;
        const float* alb = Alog_b + (size_t)layer*DI*DS;
        const float* dsf = Dskip_f + (size_t)layer*DI;
        const float* dsb = Dskip_b + (size_t)layer*DI;

        // residual += hidden; hnorm(hi/lo) = rmsnorm(residual)
        rmsnorm_step_kernel<<<ROWSZ, 256>>>(nw);

        // xz = hnorm @ Win^T  (602 x 3072, K=768)
        gemm_bf16_kernel<<<dim3(24, 5, 1), 256>>>(
            ROWSZ, 2*DI, DM, 1,
            OFF_HN, 0, OFF_WIN + (size_t)layer*3072*768, 0,
            /*xz*/0, 2*DI, 0, nullptr, nullptr, 0);

        // depthwise conv + silu (+ split), both dirs
        conv_silu_kernel<<<dim3(g1(ROWSZ*DI), 2), 256>>>(cwf, cbf, cwb, cbb);

        // x_dbl = uc @ Wx^T  (602 x 80, K=1536), split-K 8, both dirs
        zero_xdbl_kernel<<<g1(2*ROWSZ*XD), 256>>>();
        gemm_bf16_kernel<<<dim3(1, 5, 16), 256>>>(
            ROWSZ, XD, DI, 8,
            OFF_UC, SZ_UC1, OFF_WX + (size_t)layer*80*1536, SZ_WX1,
            /*xdbl*/1, XD, (size_t)ROWSZ*XD, nullptr, nullptr, 0);

        // dt slice -> packed hi/lo
        split_dt_kernel<<<g1(2*ROWSZ*DR), 256>>>();

        // delta = softplus(dt @ Wdt^T + bdt)  (602 x 1536, K=48)
        gemm_bf16_kernel<<<dim3(12, 5, 2), 256>>>(
            ROWSZ, DI, DR, 1,
            OFF_DT, SZ_DT1, OFF_WDT + (size_t)layer*1536*48, SZ_WDT1,
            /*delta*/2, DI, (size_t)ROWSZ*DI, bdf, bdb, 2);

        // selective scan, both dirs
        scan_kernel<<<dim3(DI/16, BATCH, 2), 256>>>(alf, alb, dsf, dsb);

        // y = (ys_f + ys_b) * silu(z)  (+ split)
        combine_kernel<<<g1(ROWSZ*DI), 256>>>();

        // hidden = 0.5 * y @ Wout^T  (602 x 768, K=1536), split-K 4
        zero_hidden_kernel<<<g1(ROWSZ*DM), 256>>>();
        gemm_bf16_kernel<<<dim3(6, 5, 4), 256>>>(
            ROWSZ, DM, DI, 4,
            OFF_Y, 0, OFF_WOUT + (size_t)layer*768*1536, 0,
            /*hidden*/3, DM, 0, nullptr, nullptr, 1);
    }

    // out = rmsnorm(residual + hidden) * normf_w
    final_norm_kernel<<<ROWSZ, 256>>>(normf_w, out);
}

// round 3
// speedup vs baseline: 1.6571x; 1.1113x over previous
#include <cuda_runtime.h>
#include <cuda_bf16.h>
#include <cstdint>
#include <cstddef>

// ---------------- problem constants ----------------
#define L_SEQ 301
#define BATCH 2
#define ROWSZ 602            // BATCH * L_SEQ
#define DM    768
#define DI    1536
#define DS    16
#define DR    48
#define XD    80             // DR + 2*DS
#define NPATCH 300
#define MIDP   150
#define KPATCH 12288         // 3*64*64

// ---------------- fp32 scratch ----------------
__device__ float g_residual[ROWSZ*DM];
__device__ float g_hidden  [ROWSZ*DM];
__device__ float g_xz      [ROWSZ*2*DI];
__device__ float g_uc      [2*ROWSZ*DI];
__device__ float g_xdbl    [2*ROWSZ*XD];
__device__ float g_delta   [2*ROWSZ*DI];
__device__ float g_ys      [2*ROWSZ*DI];

// ---------------- bf16-split buffers ----------------
#define OFF_WIN  0ull
#define SZ_WIN   (8ull*3072*768)
#define OFF_WOUT (OFF_WIN + SZ_WIN)
#define SZ_WOUT  (8ull*768*1536)
#define OFF_WX   (OFF_WOUT + SZ_WOUT)
#define SZ_WX1   (8ull*80*1536)
#define OFF_WDT  (OFF_WX + 2*SZ_WX1)
#define SZ_WDT1  (8ull*1536*48)
#define OFF_PW   (OFF_WDT + 2*SZ_WDT1)
#define SZ_PW    (768ull*12288)
#define WTOT     (OFF_PW + SZ_PW)

__device__ __nv_bfloat16 w_hi[WTOT];
__device__ __nv_bfloat16 w_lo[WTOT];

#define OFF_HN   0ull
#define SZ_HN    ((size_t)ROWSZ*DM)
#define OFF_UC   (OFF_HN + SZ_HN)
#define SZ_UC1   ((size_t)ROWSZ*DI)
#define OFF_Y    (OFF_UC + 2*SZ_UC1)
#define SZ_Y     ((size_t)ROWSZ*DI)
#define OFF_XIM  (OFF_Y + SZ_Y)
#define SZ_XIM   (600ull*KPATCH)
#define ATOT     (OFF_XIM + SZ_XIM)

__device__ __nv_bfloat16 a_hi[ATOT];
__device__ __nv_bfloat16 a_lo[ATOT];

// ---------------- helpers ----------------
__device__ __forceinline__ void split1(float x, __nv_bfloat16& h, __nv_bfloat16& l) {
    __nv_bfloat16 hb = __float2bfloat16(x);
    h = hb;
    l = __float2bfloat16(x - __bfloat162float(hb));
}

__device__ __forceinline__ float* Cbuf(int id) {
    switch (id) {
        case 0: return g_xz;
        case 1: return g_xdbl;
        case 2: return g_delta;
        default: return g_hidden;
    }
}

#define LDSM4(r0,r1,r2,r3,addr) \
    asm volatile("ldmatrix.sync.aligned.m8n8.x4.shared.b16 {%0,%1,%2,%3}, [%4];" \
                 : "=r"(r0),"=r"(r1),"=r"(r2),"=r"(r3) : "r"(addr))

#define MMA16816(c,a,b) \
    asm volatile("mma.sync.aligned.m16n8k16.row.col.f32.bf16.bf16.f32 " \
                 "{%0,%1,%2,%3},{%4,%5,%6,%7},{%8,%9},{%0,%1,%2,%3};" \
                 : "+f"((c)[0]),"+f"((c)[1]),"+f"((c)[2]),"+f"((c)[3]) \
                 : "r"((a)[0]),"r"((a)[1]),"r"((a)[2]),"r"((a)[3]), \
                   "r"((b)[0]),"r"((b)[1]))

#define CPA16(saddr, gaddr, nbytes) \
    asm volatile("cp.async.cg.shared.global [%0], [%1], 16, %2;" \
                 :: "r"(saddr), "l"(gaddr), "r"(nbytes))
#define CP_COMMIT() asm volatile("cp.async.commit_group;")
#define CP_WAIT0()  asm volatile("cp.async.wait_group 0;")
#define CP_WAIT1()  asm volatile("cp.async.wait_group 1;")

// ---------------- init ----------------
__global__ void init_tokens_kernel(const float* __restrict__ cls,
                                   const float* __restrict__ pos,
                                   const float* __restrict__ pb) {
    int i = blockIdx.x * 256 + threadIdx.x;
    if (i >= ROWSZ*DM) return;
    g_hidden[i] = 0.f;
    int d = i % DM;
    int l = (i / DM) % L_SEQ;
    g_residual[i] = pos[(size_t)l*DM + d] + ((l == MIDP) ? cls[d] : pb[d]);
}

// ---------------- weight split ----------------
__global__ void split_w_kernel(const float* __restrict__ src, int n4, size_t off) {
    int i = blockIdx.x * 256 + threadIdx.x;
    if (i >= n4) return;
    float4 v = ((const float4*)src)[i];
    size_t o = off + (size_t)i*4;
    split1(v.x, w_hi[o+0], w_lo[o+0]);
    split1(v.y, w_hi[o+1], w_lo[o+1]);
    split1(v.z, w_hi[o+2], w_lo[o+2]);
    split1(v.w, w_hi[o+3], w_lo[o+3]);
}

// ---------------- im2col + split ----------------
__global__ void im2col_split_kernel(const float* __restrict__ X) {
    int q = blockIdx.x * 256 + threadIdx.x;
    if (q >= 600*KPATCH/4) return;
    int m  = q / (KPATCH/4);
    int kq = (q % (KPATCH/4)) * 4;
    int c  = kq >> 12, ii = (kq >> 6) & 63, jj = kq & 63;
    int b = m / NPATCH, p = m % NPATCH;
    int py = p / 15, px = p % 15;
    float4 v = *(const float4*)(X + (((size_t)(b*3 + c)*1280 + py*64 + ii)*960
                                      + px*64 + jj));
    size_t o = OFF_XIM + (size_t)m*KPATCH + kq;
    split1(v.x, a_hi[o+0], a_lo[o+0]);
    split1(v.y, a_hi[o+1], a_lo[o+1]);
    split1(v.z, a_hi[o+2], a_lo[o+2]);
    split1(v.w, a_hi[o+3], a_lo[o+3]);
}

// ---------------- pipelined bf16-split tensor-core NT GEMM ------------------
// C[m,n] (+)= sum_k A[m,k]*B[n,k], 3-pass hi/lo, cp.async double buffer.
// requires (kend-kbeg) % 32 == 0. dyn smem = 8*128*BKP*2 bytes.
// epi: 0 store, 1 *0.5, 3 atomicAdd into residual(patch)
#define BKP 40
#define STG (128*BKP)
__global__ __launch_bounds__(256)
void gemm_pipe_kernel(int M, int N, int K, int kSplit,
                      size_t aoff, size_t adirstr,
                      size_t boff, size_t bdirstr,
                      int c_id, int ldc, size_t cdirstr, int epi) {
    extern __shared__ uint16_t smp[];
    uint16_t* As_h = smp;
    uint16_t* As_l = smp + 2*STG;
    uint16_t* Bs_h = smp + 4*STG;
    uint16_t* Bs_l = smp + 6*STG;

    int dir = blockIdx.z / kSplit;
    int ks  = blockIdx.z % kSplit;
    int Kc  = K / kSplit;
    int kbeg = ks * Kc, kend = kbeg + Kc;

    const __nv_bfloat16* Agh = a_hi + aoff + (size_t)dir*adirstr;
    const __nv_bfloat16* Agl = a_lo + aoff + (size_t)dir*adirstr;
    const __nv_bfloat16* Bgh = w_hi + boff + (size_t)dir*bdirstr;
    const __nv_bfloat16* Bgl = w_lo + boff + (size_t)dir*bdirstr;
    float* Cg = Cbuf(c_id) + (size_t)dir*cdirstr;

    int m0 = blockIdx.y * 128, n0 = blockIdx.x * 128;
    int tid = threadIdx.x;
    int lane = tid & 31, warp = tid >> 5;
    int wm = (warp >> 2) * 64;
    int wn = (warp & 3) * 32;
    int lm = lane & 7, sel = lane >> 3;

    uint32_t sAh = (uint32_t)__cvta_generic_to_shared(As_h);
    uint32_t sAl = (uint32_t)__cvta_generic_to_shared(As_l);
    uint32_t sBh = (uint32_t)__cvta_generic_to_shared(Bs_h);
    uint32_t sBl = (uint32_t)__cvta_generic_to_shared(Bs_l);

    // per-thread load coords: 2 chunks; chunk = (row, c8)
    int row0 = tid >> 2,            c80 = tid & 3;
    int row1 = (tid + 256) >> 2,    c81 = (tid + 256) & 3;

    auto load_stage = [&](int k0, int st) {
        uint32_t so = (uint32_t)(st * STG * 2);
#pragma unroll
        for (int i = 0; i < 2; i++) {
            int row = i ? row1 : row0;
            int c8  = i ? c81 : c80;
            int gk = k0 + c8*8;
            uint32_t doff = so + (uint32_t)((row*BKP + c8*8) * 2);
            int gm = m0 + row;
            int vA = (gm < M) ? 16 : 0;
            const __nv_bfloat16* pah = vA ? (Agh + (size_t)gm*K + gk) : Agh;
            const __nv_bfloat16* pal = vA ? (Agl + (size_t)gm*K + gk) : Agl;
            CPA16(sAh + doff, pah, vA);
            CPA16(sAl + doff, pal, vA);
            int gn = n0 + row;
            int vB = (gn < N) ? 16 : 0;
            const __nv_bfloat16* pbh = vB ? (Bgh + (size_t)gn*K + gk) : Bgh;
            const __nv_bfloat16* pbl = vB ? (Bgl + (size_t)gn*K + gk) : Bgl;
            CPA16(sBh + doff, pbh, vB);
            CPA16(sBl + doff, pbl, vB);
        }
    };

    float acc[4][4][4];
#pragma unroll
    for (int i = 0; i < 4; i++)
#pragma unroll
        for (int j = 0; j < 4; j++)
#pragma unroll
            for (int q = 0; q < 4; q++) acc[i][j][q] = 0.f;

    int nIter = (kend - kbeg) >> 5;
    load_stage(kbeg, 0); CP_COMMIT();

    for (int it = 0; it < nIter; it++) {
        if (it + 1 < nIter) {
            load_stage(kbeg + (it+1)*32, (it+1) & 1); CP_COMMIT();
            CP_WAIT1();
        } else {
            CP_WAIT0();
        }
        __syncthreads();

        uint32_t so = (uint32_t)((it & 1) * STG * 2);
#pragma unroll
        for (int kk = 0; kk < 2; kk++) {
            int ko = kk*16;
            uint32_t ah[4][4], al[4][4], bh[4][2], bl[4][2];
#pragma unroll
            for (int mt = 0; mt < 4; mt++) {
                int ar = wm + mt*16 + (sel & 1)*8 + lm;
                uint32_t off = so + (uint32_t)((ar*BKP + ko + (sel >> 1)*8) * 2);
                LDSM4(ah[mt][0], ah[mt][1], ah[mt][2], ah[mt][3], sAh + off);
                LDSM4(al[mt][0], al[mt][1], al[mt][2], al[mt][3], sAl + off);
            }
#pragma unroll
            for (int p = 0; p < 2; p++) {
                int br = wn + p*16 + (sel >> 1)*8 + lm;
                uint32_t off = so + (uint32_t)((br*BKP + ko + (sel & 1)*8) * 2);
                uint32_t r0, r1, r2, r3;
                LDSM4(r0, r1, r2, r3, sBh + off);
                bh[2*p][0] = r0; bh[2*p][1] = r1;
                bh[2*p+1][0] = r2; bh[2*p+1][1] = r3;
                LDSM4(r0, r1, r2, r3, sBl + off);
                bl[2*p][0] = r0; bl[2*p][1] = r1;
                bl[2*p+1][0] = r2; bl[2*p+1][1] = r3;
            }
#pragma unroll
            for (int mt = 0; mt < 4; mt++)
#pragma unroll
                for (int nt = 0; nt < 4; nt++) {
                    MMA16816(acc[mt][nt], ah[mt], bh[nt]);
                    MMA16816(acc[mt][nt], ah[mt], bl[nt]);
                    MMA16816(acc[mt][nt], al[mt], bh[nt]);
                }
        }
        __syncthreads();
    }

    bool atomic = (kSplit > 1);
#pragma unroll
    for (int mt = 0; mt < 4; mt++) {
#pragma unroll
        for (int nt = 0; nt < 4; nt++) {
            int gm0 = m0 + wm + mt*16 + (lane >> 2);
            int gn0 = n0 + wn + nt*8 + (lane & 3)*2;
#pragma unroll
            for (int q = 0; q < 4; q++) {
                int gm = gm0 + (q >> 1)*8;
                int gn = gn0 + (q & 1);
                if (gm >= M || gn >= N) continue;
                float v = acc[mt][nt][q];
                if (epi == 3) {
                    int b = gm / NPATCH, p = gm % NPATCH;
                    int l = (p < MIDP) ? p : p + 1;
                    atomicAdd(&g_residual[((size_t)(b*L_SEQ + l))*DM + gn], v);
                    continue;
                }
                if (epi == 1) v *= 0.5f;
                if (atomic) atomicAdd(&Cg[(size_t)gm*ldc + gn], v);
                else        Cg[(size_t)gm*ldc + gn] = v;
            }
        }
    }
}

// ---------------- delta GEMM: K=48, A from fp32 g_xdbl with inline split ----
// delta = softplus(dt @ Wdt^T + bdt); grid (12, 5, 2dirs). dyn smem 57,344 B.
#define BKP2 56
__global__ __launch_bounds__(256)
void gemm_dt_kernel(size_t boff, size_t bdirstr,
                    const float* __restrict__ bias0,
                    const float* __restrict__ bias1) {
    extern __shared__ uint16_t smp2[];
    uint16_t* As_h = smp2;
    uint16_t* As_l = smp2 + 128*BKP2;
    uint16_t* Bs_h = smp2 + 2*128*BKP2;
    uint16_t* Bs_l = smp2 + 3*128*BKP2;

    int dir = blockIdx.z;
    const float* Ag = g_xdbl + (size_t)dir*ROWSZ*XD;
    const __nv_bfloat16* Bgh = w_hi + boff + (size_t)dir*bdirstr;
    const __nv_bfloat16* Bgl = w_lo + boff + (size_t)dir*bdirstr;
    float* Cg = g_delta + (size_t)dir*ROWSZ*DI;
    const float* bias = dir ? bias1 : bias0;

    int m0 = blockIdx.y * 128, n0 = blockIdx.x * 128;
    int tid = threadIdx.x;
    int lane = tid & 31, warp = tid >> 5;
    int wm = (warp >> 2) * 64;
    int wn = (warp & 3) * 32;
    int lm = lane & 7, sel = lane >> 3;

    // load A (fp32 -> split): 128 rows x 12 float4-chunks = 1536, 6 per thread
#pragma unroll
    for (int j = 0; j < 6; j++) {
        int idx = tid + j*256;
        int row = idx / 12, c4 = idx % 12;
        int gm = m0 + row;
        float4 v = {0.f,0.f,0.f,0.f};
        if (gm < ROWSZ) v = *(const float4*)(Ag + (size_t)gm*XD + c4*4);
        int so = row*BKP2 + c4*4;
        split1(v.x, *(__nv_bfloat16*)&As_h[so+0], *(__nv_bfloat16*)&As_l[so+0]);
        split1(v.y, *(__nv_bfloat16*)&As_h[so+1], *(__nv_bfloat16*)&As_l[so+1]);
        split1(v.z, *(__nv_bfloat16*)&As_h[so+2], *(__nv_bfloat16*)&As_l[so+2]);
        split1(v.w, *(__nv_bfloat16*)&As_h[so+3], *(__nv_bfloat16*)&As_l[so+3]);
    }
    // load B: 128 rows x 6 uint4-chunks = 768, 3 per thread (N=1536 always in-bounds)
#pragma unroll
    for (int j = 0; j < 3; j++) {
        int idx = tid + j*256;
        int row = idx / 6, c8 = idx % 6;
        int gn = n0 + row;
        *(uint4*)&Bs_h[row*BKP2 + c8*8] = *(const uint4*)(Bgh + (size_t)gn*DR + c8*8);
        *(uint4*)&Bs_l[row*BKP2 + c8*8] = *(const uint4*)(Bgl + (size_t)gn*DR + c8*8);
    }
    __syncthreads();

    uint32_t sAh = (uint32_t)__cvta_generic_to_shared(As_h);
    uint32_t sAl = (uint32_t)__cvta_generic_to_shared(As_l);
    uint32_t sBh = (uint32_t)__cvta_generic_to_shared(Bs_h);
    uint32_t sBl = (uint32_t)__cvta_generic_to_shared(Bs_l);

    float acc[4][4][4];
#pragma unroll
    for (int i = 0; i < 4; i++)
#pragma unroll
        for (int j = 0; j < 4; j++)
#pragma unroll
            for (int q = 0; q < 4; q++) acc[i][j][q] = 0.f;

#pragma unroll
    for (int kk = 0; kk < 3; kk++) {
        int ko = kk*16;
        uint32_t ah[4][4], al[4][4], bh[4][2], bl[4][2];
#pragma unroll
        for (int mt = 0; mt < 4; mt++) {
            int ar = wm + mt*16 + (sel & 1)*8 + lm;
            uint32_t off = (uint32_t)((ar*BKP2 + ko + (sel >> 1)*8) * 2);
            LDSM4(ah[mt][0], ah[mt][1], ah[mt][2], ah[mt][3], sAh + off);
            LDSM4(al[mt][0], al[mt][1], al[mt][2], al[mt][3], sAl + off);
        }
#pragma unroll
        for (int p = 0; p < 2; p++) {
            int br = wn + p*16 + (sel >> 1)*8 + lm;
            uint32_t off = (uint32_t)((br*BKP2 + ko + (sel & 1)*8) * 2);
            uint32_t r0, r1, r2, r3;
            LDSM4(r0, r1, r2, r3, sBh + off);
            bh[2*p][0] = r0; bh[2*p][1] = r1;
            bh[2*p+1][0] = r2; bh[2*p+1][1] = r3;
            LDSM4(r0, r1, r2, r3, sBl + off);
            bl[2*p][0] = r0; bl[2*p][1] = r1;
            bl[2*p+1][0] = r2; bl[2*p+1][1] = r3;
        }
#pragma unroll
        for (int mt = 0; mt < 4; mt++)
#pragma unroll
            for (int nt = 0; nt < 4; nt++) {
                MMA16816(acc[mt][nt], ah[mt], bh[nt]);
                MMA16816(acc[mt][nt], ah[mt], bl[nt]);
                MMA16816(acc[mt][nt], al[mt], bh[nt]);
            }
    }

#pragma unroll
    for (int mt = 0; mt < 4; mt++) {
#pragma unroll
        for (int nt = 0; nt < 4; nt++) {
            int gm0 = m0 + wm + mt*16 + (lane >> 2);
            int gn0 = n0 + wn + nt*8 + (lane & 3)*2;
#pragma unroll
            for (int q = 0; q < 4; q++) {
                int gm = gm0 + (q >> 1)*8;
                int gn = gn0 + (q & 1);
                if (gm >= ROWSZ) continue;
                float v = acc[mt][nt][q] + bias[gn];
                v = (v > 20.f) ? v : log1pf(__expf(v));
                Cg[(size_t)gm*DI + gn] = v;
            }
        }
    }
}

// ---------------- fused residual-add + RMSNorm + split ---------------------
__global__ void rmsnorm_step_kernel(const float* __restrict__ nw) {
    int row = blockIdx.x;
    float* res = &g_residual[(size_t)row*DM];
    const float* hid = &g_hidden[(size_t)row*DM];
    float v[3]; float ss = 0.f;
#pragma unroll
    for (int i = 0; i < 3; i++) {
        int d = threadIdx.x + i*256;
        float t = res[d] + hid[d];
        v[i] = t; res[d] = t; ss += t*t;
    }
#pragma unroll
    for (int o = 16; o; o >>= 1) ss += __shfl_xor_sync(0xffffffffu, ss, o);
    __shared__ float sred[8];
    if ((threadIdx.x & 31) == 0) sred[threadIdx.x >> 5] = ss;
    __syncthreads();
    float total = 0.f;
#pragma unroll
    for (int i = 0; i < 8; i++) total += sred[i];
    float scale = rsqrtf(total * (1.f/DM) + 1e-5f);
#pragma unroll
    for (int i = 0; i < 3; i++) {
        int d = threadIdx.x + i*256;
        float o = v[i] * scale * nw[d];
        size_t idx = OFF_HN + (size_t)row*DM + d;
        split1(o, a_hi[idx], a_lo[idx]);
    }
}

// ---------------- final RMSNorm -> d_out ------------------------------------
__global__ void final_norm_kernel(const float* __restrict__ nf, float* __restrict__ out) {
    int row = blockIdx.x;
    const float* res = &g_residual[(size_t)row*DM];
    const float* hid = &g_hidden[(size_t)row*DM];
    float v[3]; float ss = 0.f;
#pragma unroll
    for (int i = 0; i < 3; i++) {
        int d = threadIdx.x + i*256;
        float t = res[d] + hid[d];
        v[i] = t; ss += t*t;
    }
#pragma unroll
    for (int o = 16; o; o >>= 1) ss += __shfl_xor_sync(0xffffffffu, ss, o);
    __shared__ float sred[8];
    if ((threadIdx.x & 31) == 0) sred[threadIdx.x >> 5] = ss;
    __syncthreads();
    float total = 0.f;
#pragma unroll
    for (int i = 0; i < 8; i++) total += sred[i];
    float scale = rsqrtf(total * (1.f/DM) + 1e-5f);
#pragma unroll
    for (int i = 0; i < 3; i++) {
        int d = threadIdx.x + i*256;
        out[(size_t)row*DM + d] = v[i] * scale * nf[d];
    }
}

// ---------------- depthwise conv + SiLU + split (+ zero xdbl) --------------
__global__ void conv_silu_kernel(const float* __restrict__ cwf, const float* __restrict__ cbf,
                                 const float* __restrict__ cwb, const float* __restrict__ cbb) {
    int dir = blockIdx.y;
    int idx = blockIdx.x * 256 + threadIdx.x;
    if (idx >= ROWSZ*DI) return;
    if (dir == 0 && idx < 2*ROWSZ*XD) g_xdbl[idx] = 0.f;  // fused zero-fill
    int m = idx / DI, c = idx % DI;
    int b = m / L_SEQ, l = m % L_SEQ;
    const float* w = (dir ? cwb : cwf) + (size_t)c*4;
    float s = (dir ? cbb : cbf)[c];
#pragma unroll
    for (int tap = 0; tap < 4; tap++) {
        int lt = dir ? (l + 3 - tap) : (l - 3 + tap);
        if (lt >= 0 && lt < L_SEQ)
            s += w[tap] * g_xz[((size_t)(b*L_SEQ + lt))*(2*DI) + c];
    }
    float sv = s / (1.f + __expf(-s));
    size_t o = (size_t)dir*(ROWSZ*DI) + idx;
    g_uc[o] = sv;
    split1(sv, a_hi[OFF_UC + o], a_lo[OFF_UC + o]);
}

// ---------------- selective scan --------------------------------------------
__global__ void scan_kernel(const float* __restrict__ Alog0, const float* __restrict__ Alog1,
                            const float* __restrict__ Dp0,  const float* __restrict__ Dp1) {
    int dir = blockIdx.z, b = blockIdx.y;
    int g = threadIdx.x >> 4, s = threadIdx.x & 15;
    int d = blockIdx.x * 16 + g;
    const float* Alog = dir ? Alog1 : Alog0;
    float A  = -__expf(Alog[(size_t)d*DS + s]);
    float Dv = (dir ? Dp1 : Dp0)[d];
    const float* dl = g_delta + (size_t)dir*(ROWSZ*DI);
    const float* uu = g_uc    + (size_t)dir*(ROWSZ*DI);
    const float* xd = g_xdbl  + (size_t)dir*(ROWSZ*XD);
    float* ys = g_ys + (size_t)dir*(ROWSZ*DI);
    float h = 0.f;
    int step = dir ? -1 : 1;
    int tt = dir ? (L_SEQ-1) : 0;
    size_t rowbase = (size_t)b * L_SEQ;
    size_t r = rowbase + tt;
    float delta = dl[r*DI + d], u = uu[r*DI + d];
    float Bv = xd[r*XD + DR + s], Cv = xd[r*XD + DR + DS + s];
    for (int it = 0; it < L_SEQ; it++) {
        float dn = 0.f, un = 0.f, Bn = 0.f, Cn = 0.f;
        int ttn = tt + step;
        if (it < L_SEQ-1) {
            size_t rn = rowbase + ttn;
            dn = dl[rn*DI + d]; un = uu[rn*DI + d];
            Bn = xd[rn*XD + DR + s]; Cn = xd[rn*XD + DR + DS + s];
        }
        h = __expf(delta * A) * h + (delta * u) * Bv;
        float y = h * Cv;
#pragma unroll
        for (int o = 8; o; o >>= 1) y += __shfl_xor_sync(0xffffffffu, y, o, 16);
        if (s == 0) ys[(rowbase + tt)*DI + d] = y + u * Dv;
        delta = dn; u = un; Bv = Bn; Cv = Cn; tt = ttn;
    }
}

// ---------------- combine + split (+ zero hidden) ---------------------------
__global__ void combine_kernel() {
    int idx = blockIdx.x * 256 + threadIdx.x;
    if (idx >= ROWSZ*DI) return;
    if (idx < ROWSZ*DM) g_hidden[idx] = 0.f;  // fused zero-fill
    int m = idx / DI, c = idx % DI;
    float z = g_xz[(size_t)m*(2*DI) + DI + c];
    float sv = z / (1.f + __expf(-z));
    float yv = (g_ys[idx] + g_ys[(size_t)ROWSZ*DI + idx]) * sv;
    split1(yv, a_hi[OFF_Y + idx], a_lo[OFF_Y + idx]);
}

// ---------------- launcher ---------------------------------------------------
extern "C" void kernel_launch(void* const* d_in, const int* in_sizes, int n_in,
                              void* d_out, int out_size) {
    const float* x        = (const float*)d_in[0];
    const float* patch_w  = (const float*)d_in[1];
    const float* patch_b  = (const float*)d_in[2];
    const float* cls_tok  = (const float*)d_in[3];
    const float* pos_emb  = (const float*)d_in[4];
    const float* norm_ws  = (const float*)d_in[5];
    const float* Win      = (const float*)d_in[6];
    const float* convw_f  = (const float*)d_in[7];
    const float* convb_f  = (const float*)d_in[8];
    const float* Wx_f     = (const float*)d_in[9];
    const float* Wdt_f    = (const float*)d_in[10];
    const float* bdt_f    = (const float*)d_in[11];
    const float* Alog_f   = (const float*)d_in[12];
    const float* Dskip_f  = (const float*)d_in[13];
    const float* convw_b  = (const float*)d_in[14];
    const float* convb_b  = (const float*)d_in[15];
    const float* Wx_b     = (const float*)d_in[16];
    const float* Wdt_b    = (const float*)d_in[17];
    const float* bdt_b    = (const float*)d_in[18];
    const float* Alog_b   = (const float*)d_in[19];
    const float* Dskip_b  = (const float*)d_in[20];
    const float* Wout     = (const float*)d_in[21];
    const float* normf_w  = (const float*)d_in[22];
    float* out = (float*)d_out;

    static bool attr_set = false;
    if (!attr_set) {
        cudaFuncSetAttribute(gemm_pipe_kernel,
                             cudaFuncAttributeMaxDynamicSharedMemorySize, 8*STG*2);
        cudaFuncSetAttribute(gemm_dt_kernel,
                             cudaFuncAttributeMaxDynamicSharedMemorySize, 4*128*BKP2*2);
        attr_set = true;
    }

    auto g1 = [](size_t n) { return (unsigned)((n + 255) / 256); };

    init_tokens_kernel<<<g1(ROWSZ*DM), 256>>>(cls_tok, pos_emb, patch_b);

    split_w_kernel<<<g1(SZ_WIN/4), 256>>>(Win, (int)(SZ_WIN/4), OFF_WIN);
    split_w_kernel<<<g1(SZ_WOUT/4), 256>>>(Wout, (int)(SZ_WOUT/4), OFF_WOUT);
    split_w_kernel<<<g1(SZ_WX1/4), 256>>>(Wx_f, (int)(SZ_WX1/4), OFF_WX);
    split_w_kernel<<<g1(SZ_WX1/4), 256>>>(Wx_b, (int)(SZ_WX1/4), OFF_WX + SZ_WX1);
    split_w_kernel<<<g1(SZ_WDT1/4), 256>>>(Wdt_f, (int)(SZ_WDT1/4), OFF_WDT);
    split_w_kernel<<<g1(SZ_WDT1/4), 256>>>(Wdt_b, (int)(SZ_WDT1/4), OFF_WDT + SZ_WDT1);
    split_w_kernel<<<g1(SZ_PW/4), 256>>>(patch_w, (int)(SZ_PW/4), OFF_PW);

    im2col_split_kernel<<<g1(SZ_XIM/4), 256>>>(x);
    // patch GEMM -> residual (atomic), split-K 8
    gemm_pipe_kernel<<<dim3(6, 5, 8), 256, 8*STG*2>>>(
        600, DM, KPATCH, 8, OFF_XIM, 0, OFF_PW, 0, 3, DM, 0, /*epi*/3);

    for (int layer = 0; layer < 8; layer++) {
        const float* nw  = norm_ws + (size_t)layer*DM;
        const float* cwf = convw_f + (size_t)layer*DI*4;
        const float* cbf = convb_f + (size_t)layer*DI;
        const float* cwb = convw_b + (size_t)layer*DI*4;
        const float* cbb = convb_b + (size_t)layer*DI;
        const float* bdf = bdt_f + (size_t)layer*DI;
        const float* bdb = bdt_b + (size_t)layer*DI;
        const float* alf = Alog_f + (size_t)layer*DI*DS;
        const float* alb = Alog_b + (size_t)layer*DI*DS;
        const float* dsf = Dskip_f + (size_t)layer*DI;
        const float* dsb = Dskip_b + (size_t)layer*DI;

        rmsnorm_step_kernel<<<ROWSZ, 256>>>(nw);

        // xz = hnorm @ Win^T (602 x 3072, K=768)
        gemm_pipe_kernel<<<dim3(24, 5, 1), 256, 8*STG*2>>>(
            ROWSZ, 2*DI, DM, 1, OFF_HN, 0,
            OFF_WIN + (size_t)layer*3072*768, 0, /*xz*/0, 2*DI, 0, 0);

        // conv + silu + split (+ zero xdbl)
        conv_silu_kernel<<<dim3(g1(ROWSZ*DI), 2), 256>>>(cwf, cbf, cwb, cbb);

        // x_dbl = uc @ Wx^T (602 x 80, K=1536), split-K 12, both dirs
        gemm_pipe_kernel<<<dim3(1, 5, 2*12), 256, 8*STG*2>>>(
            ROWSZ, XD, DI, 12, OFF_UC, SZ_UC1,
            OFF_WX + (size_t)layer*80*1536, SZ_WX1,
            /*xdbl*/1, XD, (size_t)ROWSZ*XD, 0);

        // delta = softplus(dt @ Wdt^T + bdt), K=48, inline fp32 split
        gemm_dt_kernel<<<dim3(12, 5, 2), 256, 4*128*BKP2*2>>>(
            OFF_WDT + (size_t)layer*1536*48, SZ_WDT1, bdf, bdb);

        // selective scan
        scan_kernel<<<dim3(DI/16, BATCH, 2), 256>>>(alf, alb, dsf, dsb);

        // combine (+ zero hidden)
        combine_kernel<<<g1(ROWSZ*DI), 256>>>();

        // hidden = 0.5 * y @ Wout^T (602 x 768, K=1536), split-K 4
        gemm_pipe_kernel<<<dim3(6, 5, 4), 256, 8*STG*2>>>(
            ROWSZ, DM, DI, 4, OFF_Y, 0,
            OFF_WOUT + (size_t)layer*768*1536, 0, /*hidden*/3, DM, 0, /*epi*/1);
    }

    final_norm_kernel<<<ROWSZ, 256>>>(normf_w, out);
}